// round 1
// baseline (speedup 1.0000x reference)
#include <cuda_runtime.h>
#include <math.h>

#define BATCH 32
#define DEPTH 12
#define CDIM 768
#define NHEADS 12
#define HD 64
#define NTOK 197
#define NPATCH 196
#define GRD 14
#define PSZ 16
#define HIDDIM 3072
#define NCLS 1000
#define IMG 224
#define HALFW 3

// ---------------- scratch (device globals; no allocation allowed) -------------
__device__ float g_xp[BATCH * NPATCH * CDIM];          // gathered patches
__device__ float g_t[BATCH * NTOK * CDIM];             // residual stream
__device__ float g_h[BATCH * NTOK * CDIM];             // LN output / patch gemm out
__device__ float g_qkv[BATCH * NTOK * 3 * CDIM];       // qkv
__device__ float g_attn[(size_t)BATCH * NHEADS * NTOK * NTOK]; // scores/probs
__device__ float g_o[BATCH * NTOK * CDIM];             // attention output
__device__ float g_mlp[BATCH * NTOK * HIDDIM];         // mlp hidden
__device__ float g_cls[BATCH * CDIM];                  // final LN of cls rows

// ---------------- SGEMM: C = A(MxK) @ B(KxN) [+bias][gelu][+resid] -----------
#define BM 128
#define BN 128
#define BK 8
#define TM 8
#define TN 8

template <bool BT, bool GELU>
__global__ void __launch_bounds__(256)
gemm_kernel(int M, int N, int K,
            const float* __restrict__ A, const float* __restrict__ B,
            const float* __restrict__ bias, const float* __restrict__ resid,
            float* __restrict__ C) {
    __shared__ float As[BK][BM];
    __shared__ float Bs[BK][BN];
    const int tid = threadIdx.x;
    const int m0 = blockIdx.y * BM;
    const int n0 = blockIdx.x * BN;
    const int tx = tid % (BN / TN);  // 0..15
    const int ty = tid / (BN / TN);  // 0..15

    float acc[TM][TN];
#pragma unroll
    for (int i = 0; i < TM; i++)
#pragma unroll
        for (int j = 0; j < TN; j++) acc[i][j] = 0.f;

    const int arow = tid / (BK / 4);        // 0..127
    const int acol = (tid % (BK / 4)) * 4;  // 0 or 4
    const int brow = tid / (BN / 4);        // 0..7
    const int bcol = (tid % (BN / 4)) * 4;  // 0..124

    for (int k0 = 0; k0 < K; k0 += BK) {
        // load A tile (BM x BK), store transposed
        {
            int gm = m0 + arow;
            float4 v = make_float4(0.f, 0.f, 0.f, 0.f);
            if (gm < M)
                v = *reinterpret_cast<const float4*>(&A[(size_t)gm * K + k0 + acol]);
            As[acol + 0][arow] = v.x;
            As[acol + 1][arow] = v.y;
            As[acol + 2][arow] = v.z;
            As[acol + 3][arow] = v.w;
        }
        // load B tile (BK x BN)
        if (!BT) {
            int gn = n0 + bcol;
            float4 v;
            if (gn + 3 < N) {
                v = *reinterpret_cast<const float4*>(&B[(size_t)(k0 + brow) * N + gn]);
            } else {
                float t0 = (gn + 0 < N) ? B[(size_t)(k0 + brow) * N + gn + 0] : 0.f;
                float t1 = (gn + 1 < N) ? B[(size_t)(k0 + brow) * N + gn + 1] : 0.f;
                float t2 = (gn + 2 < N) ? B[(size_t)(k0 + brow) * N + gn + 2] : 0.f;
                float t3 = (gn + 3 < N) ? B[(size_t)(k0 + brow) * N + gn + 3] : 0.f;
                v = make_float4(t0, t1, t2, t3);
            }
            Bs[brow][bcol + 0] = v.x;
            Bs[brow][bcol + 1] = v.y;
            Bs[brow][bcol + 2] = v.z;
            Bs[brow][bcol + 3] = v.w;
        } else {
            // B given as (N,K) row-major
            int gn = n0 + arow;
            float4 v = make_float4(0.f, 0.f, 0.f, 0.f);
            if (gn < N)
                v = *reinterpret_cast<const float4*>(&B[(size_t)gn * K + k0 + acol]);
            Bs[acol + 0][arow] = v.x;
            Bs[acol + 1][arow] = v.y;
            Bs[acol + 2][arow] = v.z;
            Bs[acol + 3][arow] = v.w;
        }
        __syncthreads();

#pragma unroll
        for (int kk = 0; kk < BK; kk++) {
            float ra[TM], rb[TN];
#pragma unroll
            for (int i = 0; i < TM; i++) ra[i] = As[kk][ty * TM + i];
#pragma unroll
            for (int j = 0; j < TN; j++) rb[j] = Bs[kk][tx * TN + j];
#pragma unroll
            for (int i = 0; i < TM; i++)
#pragma unroll
                for (int j = 0; j < TN; j++) acc[i][j] = fmaf(ra[i], rb[j], acc[i][j]);
        }
        __syncthreads();
    }

#pragma unroll
    for (int i = 0; i < TM; i++) {
        int gm = m0 + ty * TM + i;
        if (gm >= M) continue;
#pragma unroll
        for (int j = 0; j < TN; j++) {
            int gn = n0 + tx * TN + j;
            if (gn >= N) continue;
            float v = acc[i][j];
            if (bias) v += bias[gn];
            if (GELU) v = 0.5f * v * (1.f + erff(v * 0.70710678118654752f));
            if (resid) v += resid[(size_t)gm * N + gn];
            C[(size_t)gm * N + gn] = v;
        }
    }
}

// ---------------- patch gather -----------------------------------------------
__global__ void gather_kernel(const float* __restrict__ x) {
    int idx = blockIdx.x * blockDim.x + threadIdx.x;
    const int total = BATCH * NPATCH * CDIM;
    if (idx >= total) return;
    int k = idx % CDIM;
    int g = (idx / CDIM) % NPATCH;
    int b = idx / (CDIM * NPATCH);
    int ch = k / (PSZ * PSZ);
    int pr = (k / PSZ) % PSZ;
    int pc = k % PSZ;
    int gr = g / GRD;
    int gc = g % GRD;
    g_xp[idx] = x[(((size_t)b * 3 + ch) * IMG + gr * PSZ + pr) * IMG + gc * PSZ + pc];
}

// ---------------- assemble t = [cls; patches] + pos --------------------------
__global__ void assemble_kernel(const float* __restrict__ cls_tok,
                                const float* __restrict__ pos) {
    int idx = blockIdx.x * blockDim.x + threadIdx.x;
    const int total = BATCH * NTOK * CDIM;
    if (idx >= total) return;
    int c = idx % CDIM;
    int n = (idx / CDIM) % NTOK;
    int b = idx / (CDIM * NTOK);
    float v = (n == 0) ? cls_tok[c] : g_h[((size_t)b * NPATCH + n - 1) * CDIM + c];
    g_t[idx] = v + pos[(size_t)n * CDIM + c];
}

// ---------------- layernorm (row stride configurable) ------------------------
__global__ void __launch_bounds__(256)
ln_kernel(const float* __restrict__ x, long in_stride,
          const float* __restrict__ w, const float* __restrict__ b,
          float* __restrict__ y, long out_stride) {
    const float* row = x + (size_t)blockIdx.x * in_stride;
    float* out = y + (size_t)blockIdx.x * out_stride;
    int tid = threadIdx.x;
    float s = 0.f, s2 = 0.f;
#pragma unroll
    for (int i = 0; i < 3; i++) {
        float v = row[tid + i * 256];
        s += v;
        s2 += v * v;
    }
    __shared__ float red[256], red2[256];
    red[tid] = s;
    red2[tid] = s2;
    __syncthreads();
    for (int o = 128; o > 0; o >>= 1) {
        if (tid < o) {
            red[tid] += red[tid + o];
            red2[tid] += red2[tid + o];
        }
        __syncthreads();
    }
    float mu = red[0] * (1.f / CDIM);
    float var = red2[0] * (1.f / CDIM) - mu * mu;
    float rstd = rsqrtf(var + 1e-5f);
#pragma unroll
    for (int i = 0; i < 3; i++) {
        int c = tid + i * 256;
        out[c] = (row[c] - mu) * rstd * w[c] + b[c];
    }
}

// ---------------- masked attention scores ------------------------------------
__global__ void __launch_bounds__(256)
scores_kernel() {
    const int bh = blockIdx.z;
    const int b = bh / NHEADS;
    const int h = bh % NHEADS;
    const int q0 = blockIdx.y * 32;
    const int k0 = blockIdx.x * 32;
    __shared__ float qs[32][65];
    __shared__ float ks[32][65];
    const int tid = threadIdx.x;
#pragma unroll
    for (int i = 0; i < 8; i++) {
        int p = tid + i * 256;
        int r = p / 64, d = p % 64;
        int qi = q0 + r, kj = k0 + r;
        qs[r][d] = (qi < NTOK)
            ? g_qkv[((size_t)(b * NTOK + qi)) * (3 * CDIM) + 0 * CDIM + h * HD + d] : 0.f;
        ks[r][d] = (kj < NTOK)
            ? g_qkv[((size_t)(b * NTOK + kj)) * (3 * CDIM) + 1 * CDIM + h * HD + d] : 0.f;
    }
    __syncthreads();
#pragma unroll
    for (int i = 0; i < 4; i++) {
        int p = tid + i * 256;
        int r = p / 32, c = p % 32;
        int qi = q0 + r, kj = k0 + c;
        if (qi >= NTOK || kj >= NTOK) continue;
        float acc = 0.f;
#pragma unroll
        for (int d = 0; d < HD; d++) acc = fmaf(qs[r][d], ks[c][d], acc);
        acc *= 0.125f;  // hd^-0.5
        bool allowed;
        if (qi == 0 || kj == 0) {
            allowed = true;
        } else {
            int qr = (qi - 1) / GRD, qc = (qi - 1) % GRD;
            int kr = (kj - 1) / GRD, kc = (kj - 1) % GRD;
            allowed = (abs(qr - kr) <= HALFW) && (abs(qc - kc) <= HALFW);
        }
        g_attn[((size_t)bh * NTOK + qi) * NTOK + kj] = allowed ? acc : -INFINITY;
    }
}

// ---------------- row softmax (one warp per row) -----------------------------
__global__ void __launch_bounds__(256)
softmax_kernel(int rows) {
    int warp = (blockIdx.x * blockDim.x + threadIdx.x) >> 5;
    int lane = threadIdx.x & 31;
    if (warp >= rows) return;
    float* row = g_attn + (size_t)warp * NTOK;
    float vals[7];
    float mx = -INFINITY;
#pragma unroll
    for (int i = 0; i < 7; i++) {
        int j = lane + i * 32;
        vals[i] = (j < NTOK) ? row[j] : -INFINITY;
        mx = fmaxf(mx, vals[i]);
    }
#pragma unroll
    for (int o = 16; o > 0; o >>= 1) mx = fmaxf(mx, __shfl_xor_sync(0xffffffffu, mx, o));
    float s = 0.f;
#pragma unroll
    for (int i = 0; i < 7; i++) {
        vals[i] = __expf(vals[i] - mx);
        s += vals[i];
    }
#pragma unroll
    for (int o = 16; o > 0; o >>= 1) s += __shfl_xor_sync(0xffffffffu, s, o);
    float inv = 1.f / s;
#pragma unroll
    for (int i = 0; i < 7; i++) {
        int j = lane + i * 32;
        if (j < NTOK) row[j] = vals[i] * inv;
    }
}

// ---------------- O = P @ V ---------------------------------------------------
__global__ void __launch_bounds__(256)
av_kernel() {
    const int bh = blockIdx.y;
    const int b = bh / NHEADS;
    const int h = bh % NHEADS;
    const int r0 = blockIdx.x * 32;
    __shared__ float At[32][32];
    __shared__ float Vt[32][64];
    const int tid = threadIdx.x;
    const int col = tid % 64;
    const int rowg = tid / 64;  // 0..3
    float acc[8];
#pragma unroll
    for (int i = 0; i < 8; i++) acc[i] = 0.f;

    for (int k0 = 0; k0 < NTOK; k0 += 32) {
#pragma unroll
        for (int i = 0; i < 4; i++) {
            int p = tid + i * 256;
            int r = p / 32, c = p % 32;
            int qi = r0 + r, kj = k0 + c;
            At[r][c] = (qi < NTOK && kj < NTOK)
                ? g_attn[((size_t)bh * NTOK + qi) * NTOK + kj] : 0.f;
        }
#pragma unroll
        for (int i = 0; i < 8; i++) {
            int p = tid + i * 256;
            int r = p / 64, d = p % 64;
            int kj = k0 + r;
            Vt[r][d] = (kj < NTOK)
                ? g_qkv[((size_t)(b * NTOK + kj)) * (3 * CDIM) + 2 * CDIM + h * HD + d] : 0.f;
        }
        __syncthreads();
#pragma unroll
        for (int kk = 0; kk < 32; kk++) {
            float v = Vt[kk][col];
#pragma unroll
            for (int i = 0; i < 8; i++)
                acc[i] = fmaf(At[rowg * 8 + i][kk], v, acc[i]);
        }
        __syncthreads();
    }
#pragma unroll
    for (int i = 0; i < 8; i++) {
        int tok = r0 + rowg * 8 + i;
        if (tok < NTOK)
            g_o[((size_t)(b * NTOK + tok)) * CDIM + h * HD + col] = acc[i];
    }
}

// ---------------- launch helpers ---------------------------------------------
static inline dim3 gemm_grid(int M, int N) {
    return dim3((N + BN - 1) / BN, (M + BM - 1) / BM);
}

extern "C" void kernel_launch(void* const* d_in, const int* in_sizes, int n_in,
                              void* d_out, int out_size) {
    const float* x       = (const float*)d_in[0];
    const float* patch_w = (const float*)d_in[1];
    const float* patch_b = (const float*)d_in[2];
    const float* cls_tok = (const float*)d_in[3];
    const float* pos     = (const float*)d_in[4];
    const float* ln1_w   = (const float*)d_in[5];
    const float* ln1_b   = (const float*)d_in[6];
    const float* qkv_w   = (const float*)d_in[7];
    const float* proj_w  = (const float*)d_in[8];
    const float* proj_b  = (const float*)d_in[9];
    const float* ln2_w   = (const float*)d_in[10];
    const float* ln2_b   = (const float*)d_in[11];
    const float* mlp_w1  = (const float*)d_in[12];
    const float* mlp_b1  = (const float*)d_in[13];
    const float* mlp_w2  = (const float*)d_in[14];
    const float* mlp_b2  = (const float*)d_in[15];
    const float* norm_w  = (const float*)d_in[16];
    const float* norm_b  = (const float*)d_in[17];
    const float* head_w  = (const float*)d_in[18];
    const float* head_b  = (const float*)d_in[19];
    float* out = (float*)d_out;

    float *xp, *t, *h, *qkv, *o, *mlp, *cls;
    cudaGetSymbolAddress((void**)&xp, g_xp);
    cudaGetSymbolAddress((void**)&t, g_t);
    cudaGetSymbolAddress((void**)&h, g_h);
    cudaGetSymbolAddress((void**)&qkv, g_qkv);
    cudaGetSymbolAddress((void**)&o, g_o);
    cudaGetSymbolAddress((void**)&mlp, g_mlp);
    cudaGetSymbolAddress((void**)&cls, g_cls);

    const int Mtok = BATCH * NTOK;  // 6304

    // patch embed: gather -> TN gemm -> assemble(+cls,+pos)
    {
        int total = BATCH * NPATCH * CDIM;
        gather_kernel<<<(total + 255) / 256, 256>>>(x);
        gemm_kernel<true, false><<<gemm_grid(BATCH * NPATCH, CDIM), 256>>>(
            BATCH * NPATCH, CDIM, CDIM, xp, patch_w, patch_b, nullptr, h);
        int tot2 = BATCH * NTOK * CDIM;
        assemble_kernel<<<(tot2 + 255) / 256, 256>>>(cls_tok, pos);
    }

    for (int i = 0; i < DEPTH; i++) {
        // LN1
        ln_kernel<<<Mtok, 256>>>(t, CDIM, ln1_w + i * CDIM, ln1_b + i * CDIM, h, CDIM);
        // qkv
        gemm_kernel<false, false><<<gemm_grid(Mtok, 3 * CDIM), 256>>>(
            Mtok, 3 * CDIM, CDIM, h, qkv_w + (size_t)i * CDIM * 3 * CDIM,
            nullptr, nullptr, qkv);
        // scores + softmax + PV
        scores_kernel<<<dim3(7, 7, BATCH * NHEADS), 256>>>();
        {
            int rows = BATCH * NHEADS * NTOK;
            softmax_kernel<<<(rows * 32 + 255) / 256, 256>>>(rows);
        }
        av_kernel<<<dim3(7, BATCH * NHEADS), 256>>>();
        // proj + residual
        gemm_kernel<false, false><<<gemm_grid(Mtok, CDIM), 256>>>(
            Mtok, CDIM, CDIM, o, proj_w + (size_t)i * CDIM * CDIM,
            proj_b + i * CDIM, t, t);
        // LN2
        ln_kernel<<<Mtok, 256>>>(t, CDIM, ln2_w + i * CDIM, ln2_b + i * CDIM, h, CDIM);
        // mlp1 + gelu
        gemm_kernel<false, true><<<gemm_grid(Mtok, HIDDIM), 256>>>(
            Mtok, HIDDIM, CDIM, h, mlp_w1 + (size_t)i * CDIM * HIDDIM,
            mlp_b1 + i * HIDDIM, nullptr, mlp);
        // mlp2 + residual
        gemm_kernel<false, false><<<gemm_grid(Mtok, CDIM), 256>>>(
            Mtok, CDIM, HIDDIM, mlp, mlp_w2 + (size_t)i * HIDDIM * CDIM,
            mlp_b2 + i * CDIM, t, t);
    }

    // final LN over cls rows only, then head
    ln_kernel<<<BATCH, 256>>>(t, (long)NTOK * CDIM, norm_w, norm_b, cls, CDIM);
    gemm_kernel<false, false><<<gemm_grid(BATCH, NCLS), 256>>>(
        BATCH, NCLS, CDIM, cls, head_w, head_b, nullptr, out);
}

// round 2
// speedup vs baseline: 1.9628x; 1.9628x over previous
#include <cuda_runtime.h>
#include <math.h>
#include <stdint.h>

#define BATCH 32
#define DEPTH 12
#define CDIM 768
#define NHEADS 12
#define HD 64
#define NTOK 197
#define NPATCH 196
#define GRD 14
#define PSZ 16
#define HIDDIM 3072
#define NCLS 1000
#define IMG 224
#define HALFW 3

// ---------------- scratch (device globals; no allocation allowed) -------------
__device__ float g_xp[BATCH * NPATCH * CDIM];          // gathered patches
__device__ float g_t[BATCH * NTOK * CDIM];             // residual stream
__device__ float g_h[BATCH * NTOK * CDIM];             // LN output / patch gemm out
__device__ float g_qkv[BATCH * NTOK * 3 * CDIM];       // qkv
__device__ float g_attn[(size_t)BATCH * NHEADS * NTOK * NTOK]; // scores/probs
__device__ float g_o[BATCH * NTOK * CDIM];             // attention output
__device__ float g_mlp[BATCH * NTOK * HIDDIM];         // mlp hidden
__device__ float g_cls[BATCH * CDIM];                  // final LN of cls rows

// ================= TF32 tensor-core GEMM ======================================
// C(MxN) = A(MxK) @ B(KxN)  [BT: B given as (N,K) row-major]
// block 128x128x16, 8 warps, warp tile 64x32 (4x4 m16n8k8 fragments)
#define TCBM 128
#define TCBN 128
#define TCBK 16
#define TSTR (TCBM + 4)   // smem row stride (uint32 elems); 132*4B = 528B (16B aligned)

__device__ __forceinline__ uint32_t f2tf32(float x) {
    uint32_t r;
    asm("cvt.rna.tf32.f32 %0, %1;" : "=r"(r) : "f"(x));
    return r;
}

__device__ __forceinline__ void mma_tf32(float* d, const uint32_t* a, const uint32_t* b) {
    asm volatile(
        "mma.sync.aligned.m16n8k8.row.col.f32.tf32.tf32.f32 "
        "{%0,%1,%2,%3}, {%4,%5,%6,%7}, {%8,%9}, {%0,%1,%2,%3};"
        : "+f"(d[0]), "+f"(d[1]), "+f"(d[2]), "+f"(d[3])
        : "r"(a[0]), "r"(a[1]), "r"(a[2]), "r"(a[3]), "r"(b[0]), "r"(b[1]));
}

template <bool BT, bool GELU>
__global__ void __launch_bounds__(256, 2)
gemm_tc(int M, int N, int K,
        const float* __restrict__ A, const float* __restrict__ B,
        const float* __restrict__ bias, const float* __restrict__ resid,
        float* __restrict__ C) {
    __shared__ uint32_t As[TCBK][TSTR];
    __shared__ uint32_t Bs[TCBK][TSTR];
    const int tid = threadIdx.x;
    const int lane = tid & 31;
    const int warp = tid >> 5;
    const int m0 = blockIdx.y * TCBM;
    const int n0 = blockIdx.x * TCBN;
    const int wm = (warp >> 2) * 64;  // 0 or 64
    const int wn = (warp & 3) * 32;   // 0,32,64,96
    const int r = lane >> 2;          // groupID 0..7
    const int c = lane & 3;           // tid-in-group 0..3

    float acc[4][4][4];
#pragma unroll
    for (int mt = 0; mt < 4; mt++)
#pragma unroll
        for (int nt = 0; nt < 4; nt++)
#pragma unroll
            for (int i = 0; i < 4; i++) acc[mt][nt][i] = 0.f;

    const int arow = tid >> 2;        // 0..63
    const int acol = (tid & 3) << 2;  // 0,4,8,12

    for (int k0 = 0; k0 < K; k0 += TCBK) {
        // ---- load A tile (128 x 16), store k-major (transposed) ----
#pragma unroll
        for (int half = 0; half < 2; half++) {
            int mrow = arow + half * 64;
            int gm = m0 + mrow;
            float4 v = make_float4(0.f, 0.f, 0.f, 0.f);
            if (gm < M)
                v = *reinterpret_cast<const float4*>(&A[(size_t)gm * K + k0 + acol]);
            As[acol + 0][mrow] = f2tf32(v.x);
            As[acol + 1][mrow] = f2tf32(v.y);
            As[acol + 2][mrow] = f2tf32(v.z);
            As[acol + 3][mrow] = f2tf32(v.w);
        }
        // ---- load B tile ----
        if (!BT) {
            // B (KxN) row-major: 16 x 128 tile, n-contiguous, uint4 stores
            const int brow = tid >> 5;        // 0..7
            const int bcol = (tid & 31) << 2; // 0..124
#pragma unroll
            for (int half = 0; half < 2; half++) {
                int row = brow + half * 8;
                float4 v = *reinterpret_cast<const float4*>(
                    &B[(size_t)(k0 + row) * N + n0 + bcol]);
                uint4 u;
                u.x = f2tf32(v.x);
                u.y = f2tf32(v.y);
                u.z = f2tf32(v.z);
                u.w = f2tf32(v.w);
                *reinterpret_cast<uint4*>(&Bs[row][bcol]) = u;
            }
        } else {
            // B (NxK) row-major: transpose like A (N assumed multiple of 128)
#pragma unroll
            for (int half = 0; half < 2; half++) {
                int nrow = arow + half * 64;
                float4 v = *reinterpret_cast<const float4*>(
                    &B[(size_t)(n0 + nrow) * K + k0 + acol]);
                Bs[acol + 0][nrow] = f2tf32(v.x);
                Bs[acol + 1][nrow] = f2tf32(v.y);
                Bs[acol + 2][nrow] = f2tf32(v.z);
                Bs[acol + 3][nrow] = f2tf32(v.w);
            }
        }
        __syncthreads();

#pragma unroll
        for (int ks = 0; ks < TCBK; ks += 8) {
            uint32_t af[4][4], bf[4][2];
#pragma unroll
            for (int mt = 0; mt < 4; mt++) {
                int mb = wm + mt * 16 + r;
                af[mt][0] = As[ks + c][mb];
                af[mt][1] = As[ks + c][mb + 8];
                af[mt][2] = As[ks + c + 4][mb];
                af[mt][3] = As[ks + c + 4][mb + 8];
            }
#pragma unroll
            for (int nt = 0; nt < 4; nt++) {
                int nb = wn + nt * 8 + r;
                bf[nt][0] = Bs[ks + c][nb];
                bf[nt][1] = Bs[ks + c + 4][nb];
            }
#pragma unroll
            for (int mt = 0; mt < 4; mt++)
#pragma unroll
                for (int nt = 0; nt < 4; nt++)
                    mma_tf32(acc[mt][nt], af[mt], bf[nt]);
        }
        __syncthreads();
    }

    // ---- epilogue: bias / gelu / residual, float2 stores ----
#pragma unroll
    for (int mt = 0; mt < 4; mt++) {
#pragma unroll
        for (int half = 0; half < 2; half++) {
            int gm = m0 + wm + mt * 16 + r + half * 8;
            if (gm >= M) continue;
#pragma unroll
            for (int nt = 0; nt < 4; nt++) {
                int gn = n0 + wn + nt * 8 + c * 2;
                float v0 = acc[mt][nt][half * 2 + 0];
                float v1 = acc[mt][nt][half * 2 + 1];
                if (bias) {
                    v0 += bias[gn];
                    v1 += bias[gn + 1];
                }
                if (GELU) {
                    v0 = 0.5f * v0 * (1.f + erff(v0 * 0.70710678118654752f));
                    v1 = 0.5f * v1 * (1.f + erff(v1 * 0.70710678118654752f));
                }
                if (resid) {
                    const float2 rr = *reinterpret_cast<const float2*>(
                        &resid[(size_t)gm * N + gn]);
                    v0 += rr.x;
                    v1 += rr.y;
                }
                *reinterpret_cast<float2*>(&C[(size_t)gm * N + gn]) =
                    make_float2(v0, v1);
            }
        }
    }
}

// ---------------- small SIMT GEMM (kept for head: M=32, N=1000) ---------------
#define BM 128
#define BN 128
#define BK 8
#define TM 8
#define TN 8

__global__ void __launch_bounds__(256)
gemm_small(int M, int N, int K,
           const float* __restrict__ A, const float* __restrict__ B,
           const float* __restrict__ bias, float* __restrict__ C) {
    __shared__ float As[BK][BM];
    __shared__ float Bs[BK][BN];
    const int tid = threadIdx.x;
    const int m0 = blockIdx.y * BM;
    const int n0 = blockIdx.x * BN;
    const int tx = tid % (BN / TN);
    const int ty = tid / (BN / TN);

    float acc[TM][TN];
#pragma unroll
    for (int i = 0; i < TM; i++)
#pragma unroll
        for (int j = 0; j < TN; j++) acc[i][j] = 0.f;

    const int arow = tid / (BK / 4);
    const int acol = (tid % (BK / 4)) * 4;
    const int brow = tid / (BN / 4);
    const int bcol = (tid % (BN / 4)) * 4;

    for (int k0 = 0; k0 < K; k0 += BK) {
        {
            int gm = m0 + arow;
            float4 v = make_float4(0.f, 0.f, 0.f, 0.f);
            if (gm < M)
                v = *reinterpret_cast<const float4*>(&A[(size_t)gm * K + k0 + acol]);
            As[acol + 0][arow] = v.x;
            As[acol + 1][arow] = v.y;
            As[acol + 2][arow] = v.z;
            As[acol + 3][arow] = v.w;
        }
        {
            int gn = n0 + bcol;
            float t0 = (gn + 0 < N) ? B[(size_t)(k0 + brow) * N + gn + 0] : 0.f;
            float t1 = (gn + 1 < N) ? B[(size_t)(k0 + brow) * N + gn + 1] : 0.f;
            float t2 = (gn + 2 < N) ? B[(size_t)(k0 + brow) * N + gn + 2] : 0.f;
            float t3 = (gn + 3 < N) ? B[(size_t)(k0 + brow) * N + gn + 3] : 0.f;
            Bs[brow][bcol + 0] = t0;
            Bs[brow][bcol + 1] = t1;
            Bs[brow][bcol + 2] = t2;
            Bs[brow][bcol + 3] = t3;
        }
        __syncthreads();
#pragma unroll
        for (int kk = 0; kk < BK; kk++) {
            float ra[TM], rb[TN];
#pragma unroll
            for (int i = 0; i < TM; i++) ra[i] = As[kk][ty * TM + i];
#pragma unroll
            for (int j = 0; j < TN; j++) rb[j] = Bs[kk][tx * TN + j];
#pragma unroll
            for (int i = 0; i < TM; i++)
#pragma unroll
                for (int j = 0; j < TN; j++) acc[i][j] = fmaf(ra[i], rb[j], acc[i][j]);
        }
        __syncthreads();
    }
#pragma unroll
    for (int i = 0; i < TM; i++) {
        int gm = m0 + ty * TM + i;
        if (gm >= M) continue;
#pragma unroll
        for (int j = 0; j < TN; j++) {
            int gn = n0 + tx * TN + j;
            if (gn >= N) continue;
            float v = acc[i][j];
            if (bias) v += bias[gn];
            C[(size_t)gm * N + gn] = v;
        }
    }
}

// ---------------- patch gather -----------------------------------------------
__global__ void gather_kernel(const float* __restrict__ x) {
    int idx = blockIdx.x * blockDim.x + threadIdx.x;
    const int total = BATCH * NPATCH * CDIM;
    if (idx >= total) return;
    int k = idx % CDIM;
    int g = (idx / CDIM) % NPATCH;
    int b = idx / (CDIM * NPATCH);
    int ch = k / (PSZ * PSZ);
    int pr = (k / PSZ) % PSZ;
    int pc = k % PSZ;
    int gr = g / GRD;
    int gc = g % GRD;
    g_xp[idx] = x[(((size_t)b * 3 + ch) * IMG + gr * PSZ + pr) * IMG + gc * PSZ + pc];
}

// ---------------- assemble t = [cls; patches] + pos --------------------------
__global__ void assemble_kernel(const float* __restrict__ cls_tok,
                                const float* __restrict__ pos) {
    int idx = blockIdx.x * blockDim.x + threadIdx.x;
    const int total = BATCH * NTOK * CDIM;
    if (idx >= total) return;
    int c = idx % CDIM;
    int n = (idx / CDIM) % NTOK;
    int b = idx / (CDIM * NTOK);
    float v = (n == 0) ? cls_tok[c] : g_h[((size_t)b * NPATCH + n - 1) * CDIM + c];
    g_t[idx] = v + pos[(size_t)n * CDIM + c];
}

// ---------------- layernorm ---------------------------------------------------
__global__ void __launch_bounds__(256)
ln_kernel(const float* __restrict__ x, long in_stride,
          const float* __restrict__ w, const float* __restrict__ b,
          float* __restrict__ y, long out_stride) {
    const float* row = x + (size_t)blockIdx.x * in_stride;
    float* out = y + (size_t)blockIdx.x * out_stride;
    int tid = threadIdx.x;
    float s = 0.f, s2 = 0.f;
#pragma unroll
    for (int i = 0; i < 3; i++) {
        float v = row[tid + i * 256];
        s += v;
        s2 += v * v;
    }
    __shared__ float red[256], red2[256];
    red[tid] = s;
    red2[tid] = s2;
    __syncthreads();
    for (int o = 128; o > 0; o >>= 1) {
        if (tid < o) {
            red[tid] += red[tid + o];
            red2[tid] += red2[tid + o];
        }
        __syncthreads();
    }
    float mu = red[0] * (1.f / CDIM);
    float var = red2[0] * (1.f / CDIM) - mu * mu;
    float rstd = rsqrtf(var + 1e-5f);
#pragma unroll
    for (int i = 0; i < 3; i++) {
        int c = tid + i * 256;
        out[c] = (row[c] - mu) * rstd * w[c] + b[c];
    }
}

// ---------------- masked attention scores ------------------------------------
__global__ void __launch_bounds__(256)
scores_kernel() {
    const int bh = blockIdx.z;
    const int b = bh / NHEADS;
    const int h = bh % NHEADS;
    const int q0 = blockIdx.y * 32;
    const int k0 = blockIdx.x * 32;
    __shared__ float qs[32][65];
    __shared__ float ks[32][65];
    const int tid = threadIdx.x;
#pragma unroll
    for (int i = 0; i < 8; i++) {
        int p = tid + i * 256;
        int r = p / 64, d = p % 64;
        int qi = q0 + r, kj = k0 + r;
        qs[r][d] = (qi < NTOK)
            ? g_qkv[((size_t)(b * NTOK + qi)) * (3 * CDIM) + 0 * CDIM + h * HD + d] : 0.f;
        ks[r][d] = (kj < NTOK)
            ? g_qkv[((size_t)(b * NTOK + kj)) * (3 * CDIM) + 1 * CDIM + h * HD + d] : 0.f;
    }
    __syncthreads();
#pragma unroll
    for (int i = 0; i < 4; i++) {
        int p = tid + i * 256;
        int r = p / 32, c = p % 32;
        int qi = q0 + r, kj = k0 + c;
        if (qi >= NTOK || kj >= NTOK) continue;
        float acc = 0.f;
#pragma unroll
        for (int d = 0; d < HD; d++) acc = fmaf(qs[r][d], ks[c][d], acc);
        acc *= 0.125f;
        bool allowed;
        if (qi == 0 || kj == 0) {
            allowed = true;
        } else {
            int qr = (qi - 1) / GRD, qc = (qi - 1) % GRD;
            int kr = (kj - 1) / GRD, kc = (kj - 1) % GRD;
            allowed = (abs(qr - kr) <= HALFW) && (abs(qc - kc) <= HALFW);
        }
        g_attn[((size_t)bh * NTOK + qi) * NTOK + kj] = allowed ? acc : -INFINITY;
    }
}

// ---------------- row softmax -------------------------------------------------
__global__ void __launch_bounds__(256)
softmax_kernel(int rows) {
    int warp = (blockIdx.x * blockDim.x + threadIdx.x) >> 5;
    int lane = threadIdx.x & 31;
    if (warp >= rows) return;
    float* row = g_attn + (size_t)warp * NTOK;
    float vals[7];
    float mx = -INFINITY;
#pragma unroll
    for (int i = 0; i < 7; i++) {
        int j = lane + i * 32;
        vals[i] = (j < NTOK) ? row[j] : -INFINITY;
        mx = fmaxf(mx, vals[i]);
    }
#pragma unroll
    for (int o = 16; o > 0; o >>= 1) mx = fmaxf(mx, __shfl_xor_sync(0xffffffffu, mx, o));
    float s = 0.f;
#pragma unroll
    for (int i = 0; i < 7; i++) {
        vals[i] = __expf(vals[i] - mx);
        s += vals[i];
    }
#pragma unroll
    for (int o = 16; o > 0; o >>= 1) s += __shfl_xor_sync(0xffffffffu, s, o);
    float inv = 1.f / s;
#pragma unroll
    for (int i = 0; i < 7; i++) {
        int j = lane + i * 32;
        if (j < NTOK) row[j] = vals[i] * inv;
    }
}

// ---------------- O = P @ V ---------------------------------------------------
__global__ void __launch_bounds__(256)
av_kernel() {
    const int bh = blockIdx.y;
    const int b = bh / NHEADS;
    const int h = bh % NHEADS;
    const int r0 = blockIdx.x * 32;
    __shared__ float At[32][32];
    __shared__ float Vt[32][64];
    const int tid = threadIdx.x;
    const int col = tid % 64;
    const int rowg = tid / 64;
    float acc[8];
#pragma unroll
    for (int i = 0; i < 8; i++) acc[i] = 0.f;

    for (int k0 = 0; k0 < NTOK; k0 += 32) {
#pragma unroll
        for (int i = 0; i < 4; i++) {
            int p = tid + i * 256;
            int r = p / 32, c = p % 32;
            int qi = r0 + r, kj = k0 + c;
            At[r][c] = (qi < NTOK && kj < NTOK)
                ? g_attn[((size_t)bh * NTOK + qi) * NTOK + kj] : 0.f;
        }
#pragma unroll
        for (int i = 0; i < 8; i++) {
            int p = tid + i * 256;
            int r = p / 64, d = p % 64;
            int kj = k0 + r;
            Vt[r][d] = (kj < NTOK)
                ? g_qkv[((size_t)(b * NTOK + kj)) * (3 * CDIM) + 2 * CDIM + h * HD + d] : 0.f;
        }
        __syncthreads();
#pragma unroll
        for (int kk = 0; kk < 32; kk++) {
            float v = Vt[kk][col];
#pragma unroll
            for (int i = 0; i < 8; i++)
                acc[i] = fmaf(At[rowg * 8 + i][kk], v, acc[i]);
        }
        __syncthreads();
    }
#pragma unroll
    for (int i = 0; i < 8; i++) {
        int tok = r0 + rowg * 8 + i;
        if (tok < NTOK)
            g_o[((size_t)(b * NTOK + tok)) * CDIM + h * HD + col] = acc[i];
    }
}

// ---------------- launch helpers ---------------------------------------------
static inline dim3 tc_grid(int M, int N) {
    return dim3((N + TCBN - 1) / TCBN, (M + TCBM - 1) / TCBM);
}

extern "C" void kernel_launch(void* const* d_in, const int* in_sizes, int n_in,
                              void* d_out, int out_size) {
    const float* x       = (const float*)d_in[0];
    const float* patch_w = (const float*)d_in[1];
    const float* patch_b = (const float*)d_in[2];
    const float* cls_tok = (const float*)d_in[3];
    const float* pos     = (const float*)d_in[4];
    const float* ln1_w   = (const float*)d_in[5];
    const float* ln1_b   = (const float*)d_in[6];
    const float* qkv_w   = (const float*)d_in[7];
    const float* proj_w  = (const float*)d_in[8];
    const float* proj_b  = (const float*)d_in[9];
    const float* ln2_w   = (const float*)d_in[10];
    const float* ln2_b   = (const float*)d_in[11];
    const float* mlp_w1  = (const float*)d_in[12];
    const float* mlp_b1  = (const float*)d_in[13];
    const float* mlp_w2  = (const float*)d_in[14];
    const float* mlp_b2  = (const float*)d_in[15];
    const float* norm_w  = (const float*)d_in[16];
    const float* norm_b  = (const float*)d_in[17];
    const float* head_w  = (const float*)d_in[18];
    const float* head_b  = (const float*)d_in[19];
    float* out = (float*)d_out;

    float *xp, *t, *h, *qkv, *o, *mlp, *cls;
    cudaGetSymbolAddress((void**)&xp, g_xp);
    cudaGetSymbolAddress((void**)&t, g_t);
    cudaGetSymbolAddress((void**)&h, g_h);
    cudaGetSymbolAddress((void**)&qkv, g_qkv);
    cudaGetSymbolAddress((void**)&o, g_o);
    cudaGetSymbolAddress((void**)&mlp, g_mlp);
    cudaGetSymbolAddress((void**)&cls, g_cls);

    const int Mtok = BATCH * NTOK;  // 6304

    // patch embed: gather -> TN gemm (tensor core) -> assemble(+cls,+pos)
    {
        int total = BATCH * NPATCH * CDIM;
        gather_kernel<<<(total + 255) / 256, 256>>>(x);
        gemm_tc<true, false><<<tc_grid(BATCH * NPATCH, CDIM), 256>>>(
            BATCH * NPATCH, CDIM, CDIM, xp, patch_w, patch_b, nullptr, h);
        int tot2 = BATCH * NTOK * CDIM;
        assemble_kernel<<<(tot2 + 255) / 256, 256>>>(cls_tok, pos);
    }

    for (int i = 0; i < DEPTH; i++) {
        // LN1
        ln_kernel<<<Mtok, 256>>>(t, CDIM, ln1_w + i * CDIM, ln1_b + i * CDIM, h, CDIM);
        // qkv
        gemm_tc<false, false><<<tc_grid(Mtok, 3 * CDIM), 256>>>(
            Mtok, 3 * CDIM, CDIM, h, qkv_w + (size_t)i * CDIM * 3 * CDIM,
            nullptr, nullptr, qkv);
        // scores + softmax + PV
        scores_kernel<<<dim3(7, 7, BATCH * NHEADS), 256>>>();
        {
            int rows = BATCH * NHEADS * NTOK;
            softmax_kernel<<<(rows * 32 + 255) / 256, 256>>>(rows);
        }
        av_kernel<<<dim3(7, BATCH * NHEADS), 256>>>();
        // proj + residual
        gemm_tc<false, false><<<tc_grid(Mtok, CDIM), 256>>>(
            Mtok, CDIM, CDIM, o, proj_w + (size_t)i * CDIM * CDIM,
            proj_b + i * CDIM, t, t);
        // LN2
        ln_kernel<<<Mtok, 256>>>(t, CDIM, ln2_w + i * CDIM, ln2_b + i * CDIM, h, CDIM);
        // mlp1 + gelu
        gemm_tc<false, true><<<tc_grid(Mtok, HIDDIM), 256>>>(
            Mtok, HIDDIM, CDIM, h, mlp_w1 + (size_t)i * CDIM * HIDDIM,
            mlp_b1 + i * HIDDIM, nullptr, mlp);
        // mlp2 + residual
        gemm_tc<false, false><<<tc_grid(Mtok, CDIM), 256>>>(
            Mtok, CDIM, HIDDIM, mlp, mlp_w2 + (size_t)i * HIDDIM * CDIM,
            mlp_b2 + i * CDIM, t, t);
    }

    // final LN over cls rows only, then head (small SIMT gemm)
    ln_kernel<<<BATCH, 256>>>(t, (long)NTOK * CDIM, norm_w, norm_b, cls, CDIM);
    gemm_small<<<dim3((NCLS + BN - 1) / BN, 1), 256>>>(
        BATCH, NCLS, CDIM, cls, head_w, head_b, out);
}

// round 3
// speedup vs baseline: 2.4583x; 1.2525x over previous
#include <cuda_runtime.h>
#include <math.h>
#include <stdint.h>

#define BATCH 32
#define DEPTH 12
#define CDIM 768
#define NHEADS 12
#define HD 64
#define NTOK 197
#define NPATCH 196
#define GRD 14
#define PSZ 16
#define HIDDIM 3072
#define NCLS 1000
#define IMG 224
#define HALFW 3

// ---------------- scratch (device globals; no allocation allowed) -------------
__device__ float g_xp[BATCH * NPATCH * CDIM];
__device__ float g_t[BATCH * NTOK * CDIM];
__device__ float g_h[BATCH * NTOK * CDIM];
__device__ float g_qkv[BATCH * NTOK * 3 * CDIM];
__device__ float g_attn[(size_t)BATCH * NHEADS * NTOK * NTOK];
__device__ float g_o[BATCH * NTOK * CDIM];
__device__ float g_mlp[BATCH * NTOK * HIDDIM];
__device__ float g_cls[BATCH * CDIM];

// ================= TF32 tensor-core GEMM, cp.async double-buffered ===========
// C(MxN) = A(MxK) @ B(KxN)  [BT: B given as (N,K) row-major]
// block 128x128x16, 8 warps, warp tile 64x32 (4x4 m16n8k8 fragments)
#define TCBM 128
#define TCBN 128
#define TCBK 16
#define ASTR (TCBK + 4)    // A/BT smem row stride (m-major rows)
#define BSTR (TCBN + 4)    // B (k-major) smem row stride

__device__ __forceinline__ uint32_t f2tf32(float x) {
    uint32_t r;
    asm("cvt.rna.tf32.f32 %0, %1;" : "=r"(r) : "f"(x));
    return r;
}

__device__ __forceinline__ void mma_tf32(float* d, const uint32_t* a, const uint32_t* b) {
    asm volatile(
        "mma.sync.aligned.m16n8k8.row.col.f32.tf32.tf32.f32 "
        "{%0,%1,%2,%3}, {%4,%5,%6,%7}, {%8,%9}, {%0,%1,%2,%3};"
        : "+f"(d[0]), "+f"(d[1]), "+f"(d[2]), "+f"(d[3])
        : "r"(a[0]), "r"(a[1]), "r"(a[2]), "r"(a[3]), "r"(b[0]), "r"(b[1]));
}

__device__ __forceinline__ void cp16(uint32_t dst_smem, const void* src, int size) {
    asm volatile("cp.async.cg.shared.global [%0], [%1], 16, %2;\n"
                 :: "r"(dst_smem), "l"(src), "r"(size));
}
__device__ __forceinline__ void cp_commit() {
    asm volatile("cp.async.commit_group;\n");
}
template <int NWAIT>
__device__ __forceinline__ void cp_wait() {
    asm volatile("cp.async.wait_group %0;\n" :: "n"(NWAIT));
}

template <bool BT, bool GELU>
__global__ void __launch_bounds__(256, 2)
gemm_tc(int M, int N, int K,
        const float* __restrict__ A, const float* __restrict__ B,
        const float* __restrict__ bias, const float* __restrict__ resid,
        float* __restrict__ C) {
    // A: m-major [128][ASTR]; B: !BT k-major [16][BSTR], BT n-major [128][ASTR]
    __shared__ uint32_t As[2][TCBM][ASTR];
    __shared__ uint32_t Bs[2][BT ? (TCBM * ASTR) : (TCBK * BSTR)];

    const int tid = threadIdx.x;
    const int lane = tid & 31;
    const int warp = tid >> 5;
    const int m0 = blockIdx.y * TCBM;
    const int n0 = blockIdx.x * TCBN;
    const int wm = (warp >> 2) * 64;
    const int wn = (warp & 3) * 32;
    const int r = lane >> 2;
    const int c = lane & 3;

    float acc[4][4][4];
#pragma unroll
    for (int mt = 0; mt < 4; mt++)
#pragma unroll
        for (int nt = 0; nt < 4; nt++)
#pragma unroll
            for (int i = 0; i < 4; i++) acc[mt][nt][i] = 0.f;

    // loader indices: 512 16B-chunks per tile, 2 per thread
    const int lrow = tid >> 1;          // 0..127  (A / BT row)
    const int lcol = (tid & 1) << 3;    // 0 or 8  (k offset; two float4 = 8 floats... )
    // NOTE: TCBK=16 floats per row -> 4 chunks of 4 floats; use ci scheme below.

    const int iters = K / TCBK;
    int buf = 0;

    auto load_stage = [&](int stage, int k0) {
        // ---- A tile: 128 rows x 16 floats, 4 chunks/row ----
#pragma unroll
        for (int j = 0; j < 2; j++) {
            int ci = tid + j * 256;      // 0..511
            int m = ci >> 2;
            int kc = (ci & 3) << 2;
            int gm = m0 + m;
            uint32_t dst = (uint32_t)__cvta_generic_to_shared(&As[stage][m][kc]);
            const float* src = &A[(size_t)gm * K + k0 + kc];
            cp16(dst, src, (gm < M) ? 16 : 0);
        }
        // ---- B tile ----
        if (!BT) {
#pragma unroll
            for (int j = 0; j < 2; j++) {
                int ci = tid + j * 256;
                int k = ci >> 5;              // 0..15
                int nc = (ci & 31) << 2;      // 0..124
                uint32_t dst = (uint32_t)__cvta_generic_to_shared(&Bs[stage][k * BSTR + nc]);
                const float* src = &B[(size_t)(k0 + k) * N + n0 + nc];
                cp16(dst, src, 16);
            }
        } else {
#pragma unroll
            for (int j = 0; j < 2; j++) {
                int ci = tid + j * 256;
                int n = ci >> 2;
                int kc = (ci & 3) << 2;
                uint32_t dst = (uint32_t)__cvta_generic_to_shared(&Bs[stage][n * ASTR + kc]);
                const float* src = &B[(size_t)(n0 + n) * K + k0 + kc];
                cp16(dst, src, 16);
            }
        }
    };

    load_stage(0, 0);
    cp_commit();

    for (int it = 0; it < iters; ++it) {
        if (it + 1 < iters) {
            load_stage(buf ^ 1, (it + 1) * TCBK);
            cp_commit();
            cp_wait<1>();
        } else {
            cp_wait<0>();
        }
        __syncthreads();

#pragma unroll
        for (int ks = 0; ks < TCBK; ks += 8) {
            uint32_t af[4][4], bf[4][2];
#pragma unroll
            for (int mt = 0; mt < 4; mt++) {
                int mb = wm + mt * 16 + r;
                af[mt][0] = f2tf32(__uint_as_float(As[buf][mb][ks + c]));
                af[mt][1] = f2tf32(__uint_as_float(As[buf][mb + 8][ks + c]));
                af[mt][2] = f2tf32(__uint_as_float(As[buf][mb][ks + c + 4]));
                af[mt][3] = f2tf32(__uint_as_float(As[buf][mb + 8][ks + c + 4]));
            }
#pragma unroll
            for (int nt = 0; nt < 4; nt++) {
                int nb = wn + nt * 8 + r;
                if (!BT) {
                    bf[nt][0] = f2tf32(__uint_as_float(Bs[buf][(ks + c) * BSTR + nb]));
                    bf[nt][1] = f2tf32(__uint_as_float(Bs[buf][(ks + c + 4) * BSTR + nb]));
                } else {
                    bf[nt][0] = f2tf32(__uint_as_float(Bs[buf][nb * ASTR + ks + c]));
                    bf[nt][1] = f2tf32(__uint_as_float(Bs[buf][nb * ASTR + ks + c + 4]));
                }
            }
#pragma unroll
            for (int mt = 0; mt < 4; mt++)
#pragma unroll
                for (int nt = 0; nt < 4; nt++)
                    mma_tf32(acc[mt][nt], af[mt], bf[nt]);
        }
        __syncthreads();
        buf ^= 1;
    }

    // ---- epilogue: bias / gelu / residual, float2 stores ----
#pragma unroll
    for (int mt = 0; mt < 4; mt++) {
#pragma unroll
        for (int half = 0; half < 2; half++) {
            int gm = m0 + wm + mt * 16 + r + half * 8;
            if (gm >= M) continue;
#pragma unroll
            for (int nt = 0; nt < 4; nt++) {
                int gn = n0 + wn + nt * 8 + c * 2;
                float v0 = acc[mt][nt][half * 2 + 0];
                float v1 = acc[mt][nt][half * 2 + 1];
                if (bias) {
                    v0 += bias[gn];
                    v1 += bias[gn + 1];
                }
                if (GELU) {
                    v0 = 0.5f * v0 * (1.f + erff(v0 * 0.70710678118654752f));
                    v1 = 0.5f * v1 * (1.f + erff(v1 * 0.70710678118654752f));
                }
                if (resid) {
                    const float2 rr = *reinterpret_cast<const float2*>(
                        &resid[(size_t)gm * N + gn]);
                    v0 += rr.x;
                    v1 += rr.y;
                }
                *reinterpret_cast<float2*>(&C[(size_t)gm * N + gn]) =
                    make_float2(v0, v1);
            }
        }
    }
}

// ---------------- small SIMT GEMM (head: M=32, N=1000) ------------------------
#define BM 128
#define BN 128
#define BK 8
#define TM 8
#define TN 8

__global__ void __launch_bounds__(256)
gemm_small(int M, int N, int K,
           const float* __restrict__ A, const float* __restrict__ B,
           const float* __restrict__ bias, float* __restrict__ C) {
    __shared__ float As[BK][BM];
    __shared__ float Bs[BK][BN];
    const int tid = threadIdx.x;
    const int m0 = blockIdx.y * BM;
    const int n0 = blockIdx.x * BN;
    const int tx = tid % (BN / TN);
    const int ty = tid / (BN / TN);

    float acc[TM][TN];
#pragma unroll
    for (int i = 0; i < TM; i++)
#pragma unroll
        for (int j = 0; j < TN; j++) acc[i][j] = 0.f;

    const int arow = tid / (BK / 4);
    const int acol = (tid % (BK / 4)) * 4;
    const int brow = tid / (BN / 4);
    const int bcol = (tid % (BN / 4)) * 4;

    for (int k0 = 0; k0 < K; k0 += BK) {
        {
            int gm = m0 + arow;
            float4 v = make_float4(0.f, 0.f, 0.f, 0.f);
            if (gm < M)
                v = *reinterpret_cast<const float4*>(&A[(size_t)gm * K + k0 + acol]);
            As[acol + 0][arow] = v.x;
            As[acol + 1][arow] = v.y;
            As[acol + 2][arow] = v.z;
            As[acol + 3][arow] = v.w;
        }
        {
            int gn = n0 + bcol;
            float t0 = (gn + 0 < N) ? B[(size_t)(k0 + brow) * N + gn + 0] : 0.f;
            float t1 = (gn + 1 < N) ? B[(size_t)(k0 + brow) * N + gn + 1] : 0.f;
            float t2 = (gn + 2 < N) ? B[(size_t)(k0 + brow) * N + gn + 2] : 0.f;
            float t3 = (gn + 3 < N) ? B[(size_t)(k0 + brow) * N + gn + 3] : 0.f;
            Bs[brow][bcol + 0] = t0;
            Bs[brow][bcol + 1] = t1;
            Bs[brow][bcol + 2] = t2;
            Bs[brow][bcol + 3] = t3;
        }
        __syncthreads();
#pragma unroll
        for (int kk = 0; kk < BK; kk++) {
            float ra[TM], rb[TN];
#pragma unroll
            for (int i = 0; i < TM; i++) ra[i] = As[kk][ty * TM + i];
#pragma unroll
            for (int j = 0; j < TN; j++) rb[j] = Bs[kk][tx * TN + j];
#pragma unroll
            for (int i = 0; i < TM; i++)
#pragma unroll
                for (int j = 0; j < TN; j++) acc[i][j] = fmaf(ra[i], rb[j], acc[i][j]);
        }
        __syncthreads();
    }
#pragma unroll
    for (int i = 0; i < TM; i++) {
        int gm = m0 + ty * TM + i;
        if (gm >= M) continue;
#pragma unroll
        for (int j = 0; j < TN; j++) {
            int gn = n0 + tx * TN + j;
            if (gn >= N) continue;
            float v = acc[i][j];
            if (bias) v += bias[gn];
            C[(size_t)gm * N + gn] = v;
        }
    }
}

// ---------------- patch gather -----------------------------------------------
__global__ void gather_kernel(const float* __restrict__ x) {
    int idx = blockIdx.x * blockDim.x + threadIdx.x;
    const int total = BATCH * NPATCH * CDIM;
    if (idx >= total) return;
    int k = idx % CDIM;
    int g = (idx / CDIM) % NPATCH;
    int b = idx / (CDIM * NPATCH);
    int ch = k / (PSZ * PSZ);
    int pr = (k / PSZ) % PSZ;
    int pc = k % PSZ;
    int gr = g / GRD;
    int gc = g % GRD;
    g_xp[idx] = x[(((size_t)b * 3 + ch) * IMG + gr * PSZ + pr) * IMG + gc * PSZ + pc];
}

// ---------------- assemble t = [cls; patches] + pos --------------------------
__global__ void assemble_kernel(const float* __restrict__ cls_tok,
                                const float* __restrict__ pos) {
    int idx = blockIdx.x * blockDim.x + threadIdx.x;
    const int total = BATCH * NTOK * CDIM;
    if (idx >= total) return;
    int c = idx % CDIM;
    int n = (idx / CDIM) % NTOK;
    int b = idx / (CDIM * NTOK);
    float v = (n == 0) ? cls_tok[c] : g_h[((size_t)b * NPATCH + n - 1) * CDIM + c];
    g_t[idx] = v + pos[(size_t)n * CDIM + c];
}

// ---------------- layernorm ---------------------------------------------------
__global__ void __launch_bounds__(256)
ln_kernel(const float* __restrict__ x, long in_stride,
          const float* __restrict__ w, const float* __restrict__ b,
          float* __restrict__ y, long out_stride) {
    const float* row = x + (size_t)blockIdx.x * in_stride;
    float* out = y + (size_t)blockIdx.x * out_stride;
    int tid = threadIdx.x;
    float s = 0.f, s2 = 0.f;
#pragma unroll
    for (int i = 0; i < 3; i++) {
        float v = row[tid + i * 256];
        s += v;
        s2 += v * v;
    }
    __shared__ float red[256], red2[256];
    red[tid] = s;
    red2[tid] = s2;
    __syncthreads();
    for (int o = 128; o > 0; o >>= 1) {
        if (tid < o) {
            red[tid] += red[tid + o];
            red2[tid] += red2[tid + o];
        }
        __syncthreads();
    }
    float mu = red[0] * (1.f / CDIM);
    float var = red2[0] * (1.f / CDIM) - mu * mu;
    float rstd = rsqrtf(var + 1e-5f);
#pragma unroll
    for (int i = 0; i < 3; i++) {
        int c = tid + i * 256;
        out[c] = (row[c] - mu) * rstd * w[c] + b[c];
    }
}

// ---------------- masked attention scores ------------------------------------
__global__ void __launch_bounds__(256)
scores_kernel() {
    const int bh = blockIdx.z;
    const int b = bh / NHEADS;
    const int h = bh % NHEADS;
    const int q0 = blockIdx.y * 32;
    const int k0 = blockIdx.x * 32;
    __shared__ float qs[32][65];
    __shared__ float ks[32][65];
    const int tid = threadIdx.x;
#pragma unroll
    for (int i = 0; i < 8; i++) {
        int p = tid + i * 256;
        int r = p / 64, d = p % 64;
        int qi = q0 + r, kj = k0 + r;
        qs[r][d] = (qi < NTOK)
            ? g_qkv[((size_t)(b * NTOK + qi)) * (3 * CDIM) + 0 * CDIM + h * HD + d] : 0.f;
        ks[r][d] = (kj < NTOK)
            ? g_qkv[((size_t)(b * NTOK + kj)) * (3 * CDIM) + 1 * CDIM + h * HD + d] : 0.f;
    }
    __syncthreads();
#pragma unroll
    for (int i = 0; i < 4; i++) {
        int p = tid + i * 256;
        int r = p / 32, c = p % 32;
        int qi = q0 + r, kj = k0 + c;
        if (qi >= NTOK || kj >= NTOK) continue;
        float acc = 0.f;
#pragma unroll
        for (int d = 0; d < HD; d++) acc = fmaf(qs[r][d], ks[c][d], acc);
        acc *= 0.125f;
        bool allowed;
        if (qi == 0 || kj == 0) {
            allowed = true;
        } else {
            int qr = (qi - 1) / GRD, qc = (qi - 1) % GRD;
            int kr = (kj - 1) / GRD, kc = (kj - 1) % GRD;
            allowed = (abs(qr - kr) <= HALFW) && (abs(qc - kc) <= HALFW);
        }
        g_attn[((size_t)bh * NTOK + qi) * NTOK + kj] = allowed ? acc : -INFINITY;
    }
}

// ---------------- row softmax -------------------------------------------------
__global__ void __launch_bounds__(256)
softmax_kernel(int rows) {
    int warp = (blockIdx.x * blockDim.x + threadIdx.x) >> 5;
    int lane = threadIdx.x & 31;
    if (warp >= rows) return;
    float* row = g_attn + (size_t)warp * NTOK;
    float vals[7];
    float mx = -INFINITY;
#pragma unroll
    for (int i = 0; i < 7; i++) {
        int j = lane + i * 32;
        vals[i] = (j < NTOK) ? row[j] : -INFINITY;
        mx = fmaxf(mx, vals[i]);
    }
#pragma unroll
    for (int o = 16; o > 0; o >>= 1) mx = fmaxf(mx, __shfl_xor_sync(0xffffffffu, mx, o));
    float s = 0.f;
#pragma unroll
    for (int i = 0; i < 7; i++) {
        vals[i] = __expf(vals[i] - mx);
        s += vals[i];
    }
#pragma unroll
    for (int o = 16; o > 0; o >>= 1) s += __shfl_xor_sync(0xffffffffu, s, o);
    float inv = 1.f / s;
#pragma unroll
    for (int i = 0; i < 7; i++) {
        int j = lane + i * 32;
        if (j < NTOK) row[j] = vals[i] * inv;
    }
}

// ---------------- O = P @ V ---------------------------------------------------
__global__ void __launch_bounds__(256)
av_kernel() {
    const int bh = blockIdx.y;
    const int b = bh / NHEADS;
    const int h = bh % NHEADS;
    const int r0 = blockIdx.x * 32;
    __shared__ float At[32][32];
    __shared__ float Vt[32][64];
    const int tid = threadIdx.x;
    const int col = tid % 64;
    const int rowg = tid / 64;
    float acc[8];
#pragma unroll
    for (int i = 0; i < 8; i++) acc[i] = 0.f;

    for (int k0 = 0; k0 < NTOK; k0 += 32) {
#pragma unroll
        for (int i = 0; i < 4; i++) {
            int p = tid + i * 256;
            int r = p / 32, c = p % 32;
            int qi = r0 + r, kj = k0 + c;
            At[r][c] = (qi < NTOK && kj < NTOK)
                ? g_attn[((size_t)bh * NTOK + qi) * NTOK + kj] : 0.f;
        }
#pragma unroll
        for (int i = 0; i < 8; i++) {
            int p = tid + i * 256;
            int r = p / 64, d = p % 64;
            int kj = k0 + r;
            Vt[r][d] = (kj < NTOK)
                ? g_qkv[((size_t)(b * NTOK + kj)) * (3 * CDIM) + 2 * CDIM + h * HD + d] : 0.f;
        }
        __syncthreads();
#pragma unroll
        for (int kk = 0; kk < 32; kk++) {
            float v = Vt[kk][col];
#pragma unroll
            for (int i = 0; i < 8; i++)
                acc[i] = fmaf(At[rowg * 8 + i][kk], v, acc[i]);
        }
        __syncthreads();
    }
#pragma unroll
    for (int i = 0; i < 8; i++) {
        int tok = r0 + rowg * 8 + i;
        if (tok < NTOK)
            g_o[((size_t)(b * NTOK + tok)) * CDIM + h * HD + col] = acc[i];
    }
}

// ---------------- launch helpers ---------------------------------------------
static inline dim3 tc_grid(int M, int N) {
    return dim3((N + TCBN - 1) / TCBN, (M + TCBM - 1) / TCBM);
}

extern "C" void kernel_launch(void* const* d_in, const int* in_sizes, int n_in,
                              void* d_out, int out_size) {
    const float* x       = (const float*)d_in[0];
    const float* patch_w = (const float*)d_in[1];
    const float* patch_b = (const float*)d_in[2];
    const float* cls_tok = (const float*)d_in[3];
    const float* pos     = (const float*)d_in[4];
    const float* ln1_w   = (const float*)d_in[5];
    const float* ln1_b   = (const float*)d_in[6];
    const float* qkv_w   = (const float*)d_in[7];
    const float* proj_w  = (const float*)d_in[8];
    const float* proj_b  = (const float*)d_in[9];
    const float* ln2_w   = (const float*)d_in[10];
    const float* ln2_b   = (const float*)d_in[11];
    const float* mlp_w1  = (const float*)d_in[12];
    const float* mlp_b1  = (const float*)d_in[13];
    const float* mlp_w2  = (const float*)d_in[14];
    const float* mlp_b2  = (const float*)d_in[15];
    const float* norm_w  = (const float*)d_in[16];
    const float* norm_b  = (const float*)d_in[17];
    const float* head_w  = (const float*)d_in[18];
    const float* head_b  = (const float*)d_in[19];
    float* out = (float*)d_out;

    float *xp, *t, *h, *qkv, *o, *mlp, *cls;
    cudaGetSymbolAddress((void**)&xp, g_xp);
    cudaGetSymbolAddress((void**)&t, g_t);
    cudaGetSymbolAddress((void**)&h, g_h);
    cudaGetSymbolAddress((void**)&qkv, g_qkv);
    cudaGetSymbolAddress((void**)&o, g_o);
    cudaGetSymbolAddress((void**)&mlp, g_mlp);
    cudaGetSymbolAddress((void**)&cls, g_cls);

    const int Mtok = BATCH * NTOK;  // 6304

    // patch embed
    {
        int total = BATCH * NPATCH * CDIM;
        gather_kernel<<<(total + 255) / 256, 256>>>(x);
        gemm_tc<true, false><<<tc_grid(BATCH * NPATCH, CDIM), 256>>>(
            BATCH * NPATCH, CDIM, CDIM, xp, patch_w, patch_b, nullptr, h);
        int tot2 = BATCH * NTOK * CDIM;
        assemble_kernel<<<(tot2 + 255) / 256, 256>>>(cls_tok, pos);
    }

    for (int i = 0; i < DEPTH; i++) {
        ln_kernel<<<Mtok, 256>>>(t, CDIM, ln1_w + i * CDIM, ln1_b + i * CDIM, h, CDIM);
        gemm_tc<false, false><<<tc_grid(Mtok, 3 * CDIM), 256>>>(
            Mtok, 3 * CDIM, CDIM, h, qkv_w + (size_t)i * CDIM * 3 * CDIM,
            nullptr, nullptr, qkv);
        scores_kernel<<<dim3(7, 7, BATCH * NHEADS), 256>>>();
        {
            int rows = BATCH * NHEADS * NTOK;
            softmax_kernel<<<(rows * 32 + 255) / 256, 256>>>(rows);
        }
        av_kernel<<<dim3(7, BATCH * NHEADS), 256>>>();
        gemm_tc<false, false><<<tc_grid(Mtok, CDIM), 256>>>(
            Mtok, CDIM, CDIM, o, proj_w + (size_t)i * CDIM * CDIM,
            proj_b + i * CDIM, t, t);
        ln_kernel<<<Mtok, 256>>>(t, CDIM, ln2_w + i * CDIM, ln2_b + i * CDIM, h, CDIM);
        gemm_tc<false, true><<<tc_grid(Mtok, HIDDIM), 256>>>(
            Mtok, HIDDIM, CDIM, h, mlp_w1 + (size_t)i * CDIM * HIDDIM,
            mlp_b1 + i * HIDDIM, nullptr, mlp);
        gemm_tc<false, false><<<tc_grid(Mtok, CDIM), 256>>>(
            Mtok, CDIM, HIDDIM, mlp, mlp_w2 + (size_t)i * HIDDIM * CDIM,
            mlp_b2 + i * CDIM, t, t);
    }

    ln_kernel<<<BATCH, 256>>>(t, (long)NTOK * CDIM, norm_w, norm_b, cls, CDIM);
    gemm_small<<<dim3((NCLS + BN - 1) / BN, 1), 256>>>(
        BATCH, NCLS, CDIM, cls, head_w, head_b, out);
}